// round 3
// baseline (speedup 1.0000x reference)
#include <cuda_runtime.h>

// OTTT step: s, u_new = LIF(sig_tau*u + x@W + b); a_hat_new = sig_tau*a_hat + x
// Inputs (metadata order): W [8192*8192] f32, b [8192], u [8192], a_hat [8192], x [8192]
// Output: flat [s(8192) | u_new(8192) | a_hat_new(8192)] f32
//
// Single fused kernel: split-K GEMV partials + last-CTA-done reduction/epilogue.

#define IN_DIM  8192
#define OUT_DIM 8192
#define SPLITS  64
#define ROWS_PER_SPLIT (IN_DIM / SPLITS)   // 128
#define TPB     256
#define JPT     4                          // columns per thread (float4)
#define JPB     (TPB * JPT)                // 1024 columns per block
#define JBLOCKS (OUT_DIM / JPB)            // 8

// sigmoid(2.0)
#define SIG_TAU 0.8807970779778823f
#define V_TH    1.0f

// split-K partial sums (2 MB scratch) + per-j-block arrival counters
__device__ float g_part[(size_t)SPLITS * OUT_DIM];
__device__ unsigned int g_cnt[JBLOCKS];    // zero-init; reset to 0 by reducer each launch

__global__ void __launch_bounds__(TPB) ottt_fused(
    const float* __restrict__ W, const float* __restrict__ x,
    const float* __restrict__ b, const float* __restrict__ u,
    const float* __restrict__ a_hat, float* __restrict__ out)
{
    const int jb    = blockIdx.x;           // 0..7
    const int split = blockIdx.y;           // 0..63
    const int j0    = jb * JPB + threadIdx.x * JPT;
    const int i0    = split * ROWS_PER_SPLIT;
    const int c4    = j0 >> 2;              // float4 column index

    __shared__ float xs[ROWS_PER_SPLIT];
    for (int t = threadIdx.x; t < ROWS_PER_SPLIT; t += TPB)
        xs[t] = x[i0 + t];
    __syncthreads();

    const float4* __restrict__ Wv =
        reinterpret_cast<const float4*>(W + (size_t)i0 * OUT_DIM + j0);
    const size_t row_stride_v4 = OUT_DIM / 4;

    float ax = 0.f, ay = 0.f, az = 0.f, aw = 0.f;

    #pragma unroll 8
    for (int r = 0; r < ROWS_PER_SPLIT; ++r) {
        // streaming load: W is 268MB, never reused — evict-first in L2
        float4 w = __ldcs(Wv + (size_t)r * row_stride_v4);
        float xv = xs[r];
        ax = fmaf(xv, w.x, ax);
        ay = fmaf(xv, w.y, ay);
        az = fmaf(xv, w.z, az);
        aw = fmaf(xv, w.w, aw);
    }

    // publish partial (store bypasses L1; globally visible after fence)
    float4 acc = make_float4(ax, ay, az, aw);
    reinterpret_cast<float4*>(g_part + (size_t)split * OUT_DIM)[c4] = acc;

    // --- last-CTA-done election for this j-block ---
    __threadfence();   // make our partial visible before signaling arrival
    __shared__ int is_last;
    if (threadIdx.x == 0) {
        unsigned int old = atomicAdd(&g_cnt[jb], 1u);
        is_last = (old == SPLITS - 1) ? 1 : 0;
    }
    __syncthreads();
    if (!is_last) return;

    // we are the reducer for columns [jb*JPB, (jb+1)*JPB)
    __threadfence();   // acquire: all partials for this jb are visible

    float4 t = make_float4(0.f, 0.f, 0.f, 0.f);
    const float4* __restrict__ Pv = reinterpret_cast<const float4*>(g_part);
    #pragma unroll 8
    for (int s = 0; s < SPLITS; ++s) {       // fixed order => deterministic sum
        float4 p = __ldcg(Pv + (size_t)s * row_stride_v4 + c4);
        t.x += p.x; t.y += p.y; t.z += p.z; t.w += p.w;
    }

    const float4 bv = reinterpret_cast<const float4*>(b)[c4];
    const float4 uv = reinterpret_cast<const float4*>(u)[c4];

    float4 upre, sv, unew;
    upre.x = fmaf(SIG_TAU, uv.x, t.x + bv.x);
    upre.y = fmaf(SIG_TAU, uv.y, t.y + bv.y);
    upre.z = fmaf(SIG_TAU, uv.z, t.z + bv.z);
    upre.w = fmaf(SIG_TAU, uv.w, t.w + bv.w);
    sv.x = (upre.x >= V_TH) ? 1.0f : 0.0f;
    sv.y = (upre.y >= V_TH) ? 1.0f : 0.0f;
    sv.z = (upre.z >= V_TH) ? 1.0f : 0.0f;
    sv.w = (upre.w >= V_TH) ? 1.0f : 0.0f;
    unew.x = upre.x - sv.x * V_TH;
    unew.y = upre.y - sv.y * V_TH;
    unew.z = upre.z - sv.z * V_TH;
    unew.w = upre.w - sv.w * V_TH;

    reinterpret_cast<float4*>(out)[c4]           = sv;
    reinterpret_cast<float4*>(out + OUT_DIM)[c4] = unew;

    // a_hat_new = sig_tau*a_hat + x  (IN_DIM == OUT_DIM, same column range)
    const float4 av = reinterpret_cast<const float4*>(a_hat)[c4];
    const float4 xv = reinterpret_cast<const float4*>(x)[c4];
    float4 an;
    an.x = fmaf(SIG_TAU, av.x, xv.x);
    an.y = fmaf(SIG_TAU, av.y, xv.y);
    an.z = fmaf(SIG_TAU, av.z, xv.z);
    an.w = fmaf(SIG_TAU, av.w, xv.w);
    reinterpret_cast<float4*>(out + 2 * OUT_DIM)[c4] = an;

    // reset counter for the next graph replay (kernel boundary flushes it)
    __syncthreads();
    if (threadIdx.x == 0) g_cnt[jb] = 0u;
}

extern "C" void kernel_launch(void* const* d_in, const int* in_sizes, int n_in,
                              void* d_out, int out_size)
{
    const float* W     = (const float*)d_in[0];
    const float* b     = (const float*)d_in[1];
    const float* u     = (const float*)d_in[2];
    const float* a_hat = (const float*)d_in[3];
    const float* x     = (const float*)d_in[4];
    float* out = (float*)d_out;

    dim3 grid(JBLOCKS, SPLITS);
    ottt_fused<<<grid, TPB>>>(W, x, b, u, a_hat, out);
}

// round 4
// speedup vs baseline: 1.0950x; 1.0950x over previous
#include <cuda_runtime.h>

// OTTT step: s, u_new = LIF(sig_tau*u + x@W + b); a_hat_new = sig_tau*a_hat + x
// Inputs (metadata order): W [8192*8192] f32, b [8192], u [8192], a_hat [8192], x [8192]
// Output: flat [s(8192) | u_new(8192) | a_hat_new(8192)] f32

#define IN_DIM  8192
#define OUT_DIM 8192
#define SPLITS  64
#define ROWS_PER_SPLIT (IN_DIM / SPLITS)   // 128
#define TPB     256
#define JPT     4                          // columns per thread (float4)
#define JPB     (TPB * JPT)                // 1024 columns per block
#define JBLOCKS (OUT_DIM / JPB)            // 8

// sigmoid(2.0)
#define SIG_TAU 0.8807970779778823f
#define V_TH    1.0f

// split-K partial sums (2 MB scratch; __device__ global per allocation rules)
__device__ float g_part[(size_t)SPLITS * OUT_DIM];

__global__ void __launch_bounds__(TPB) gemv_partial(
    const float* __restrict__ W, const float* __restrict__ x)
{
    const int jb    = blockIdx.x;           // 0..7
    const int split = blockIdx.y;           // 0..63
    const int j0    = jb * JPB + threadIdx.x * JPT;
    const int i0    = split * ROWS_PER_SPLIT;

    __shared__ float xs[ROWS_PER_SPLIT];
    for (int t = threadIdx.x; t < ROWS_PER_SPLIT; t += TPB)
        xs[t] = x[i0 + t];
    __syncthreads();

    const float4* __restrict__ Wv =
        reinterpret_cast<const float4*>(W + (size_t)i0 * OUT_DIM + j0);
    const size_t row_stride_v4 = OUT_DIM / 4;

    float ax = 0.f, ay = 0.f, az = 0.f, aw = 0.f;

    #pragma unroll 8
    for (int r = 0; r < ROWS_PER_SPLIT; ++r) {
        // streaming load: W is 268MB, never reused — evict-first in L2
        float4 w = __ldcs(Wv + (size_t)r * row_stride_v4);
        float xv = xs[r];
        ax = fmaf(xv, w.x, ax);
        ay = fmaf(xv, w.y, ay);
        az = fmaf(xv, w.z, az);
        aw = fmaf(xv, w.w, aw);
    }

    float4 acc = make_float4(ax, ay, az, aw);
    *reinterpret_cast<float4*>(g_part + (size_t)split * OUT_DIM + j0) = acc;
}

// Epilogue: one warp per float4 column. 2048 warps = 256 CTAs x 256 threads.
// Each lane loads splits {lane, lane+32} (2 x LDG.128), butterfly shfl reduce
// (fixed association order -> deterministic), lane 0 writes s/u_new, lane 1 a_hat.
#define EPI_TPB    256
#define EPI_BLOCKS (OUT_DIM / 4 / (EPI_TPB / 32))   // 2048 warps / 8 per CTA = 256

__global__ void __launch_bounds__(EPI_TPB) lif_epilogue(
    const float* __restrict__ b, const float* __restrict__ u,
    const float* __restrict__ a_hat, const float* __restrict__ x,
    float* __restrict__ out)
{
    const int warp = (blockIdx.x * EPI_TPB + threadIdx.x) >> 5;  // 0..2047
    const int lane = threadIdx.x & 31;
    const int c4   = warp;                       // float4 column index

    const float4* __restrict__ Pv = reinterpret_cast<const float4*>(g_part);
    const size_t row_v4 = OUT_DIM / 4;

    float4 p0 = Pv[(size_t)lane * row_v4 + c4];
    float4 p1 = Pv[(size_t)(lane + 32) * row_v4 + c4];
    float4 t;
    t.x = p0.x + p1.x; t.y = p0.y + p1.y;
    t.z = p0.z + p1.z; t.w = p0.w + p1.w;

    #pragma unroll
    for (int off = 16; off > 0; off >>= 1) {
        t.x += __shfl_xor_sync(0xffffffffu, t.x, off);
        t.y += __shfl_xor_sync(0xffffffffu, t.y, off);
        t.z += __shfl_xor_sync(0xffffffffu, t.z, off);
        t.w += __shfl_xor_sync(0xffffffffu, t.w, off);
    }

    if (lane == 0) {
        const float4 bv = reinterpret_cast<const float4*>(b)[c4];
        const float4 uv = reinterpret_cast<const float4*>(u)[c4];

        float4 upre, sv, unew;
        upre.x = fmaf(SIG_TAU, uv.x, t.x + bv.x);
        upre.y = fmaf(SIG_TAU, uv.y, t.y + bv.y);
        upre.z = fmaf(SIG_TAU, uv.z, t.z + bv.z);
        upre.w = fmaf(SIG_TAU, uv.w, t.w + bv.w);
        sv.x = (upre.x >= V_TH) ? 1.0f : 0.0f;
        sv.y = (upre.y >= V_TH) ? 1.0f : 0.0f;
        sv.z = (upre.z >= V_TH) ? 1.0f : 0.0f;
        sv.w = (upre.w >= V_TH) ? 1.0f : 0.0f;
        unew.x = upre.x - sv.x * V_TH;
        unew.y = upre.y - sv.y * V_TH;
        unew.z = upre.z - sv.z * V_TH;
        unew.w = upre.w - sv.w * V_TH;

        reinterpret_cast<float4*>(out)[c4]           = sv;
        reinterpret_cast<float4*>(out + OUT_DIM)[c4] = unew;
    } else if (lane == 1) {
        // a_hat_new = sig_tau*a_hat + x  (IN_DIM == OUT_DIM, same column range)
        const float4 av = reinterpret_cast<const float4*>(a_hat)[c4];
        const float4 xv = reinterpret_cast<const float4*>(x)[c4];
        float4 an;
        an.x = fmaf(SIG_TAU, av.x, xv.x);
        an.y = fmaf(SIG_TAU, av.y, xv.y);
        an.z = fmaf(SIG_TAU, av.z, xv.z);
        an.w = fmaf(SIG_TAU, av.w, xv.w);
        reinterpret_cast<float4*>(out + 2 * OUT_DIM)[c4] = an;
    }
}

extern "C" void kernel_launch(void* const* d_in, const int* in_sizes, int n_in,
                              void* d_out, int out_size)
{
    const float* W     = (const float*)d_in[0];
    const float* b     = (const float*)d_in[1];
    const float* u     = (const float*)d_in[2];
    const float* a_hat = (const float*)d_in[3];
    const float* x     = (const float*)d_in[4];
    float* out = (float*)d_out;

    dim3 grid(JBLOCKS, SPLITS);
    gemv_partial<<<grid, TPB>>>(W, x);
    lif_epilogue<<<EPI_BLOCKS, EPI_TPB>>>(b, u, a_hat, x, out);
}